// round 8
// baseline (speedup 1.0000x reference)
#include <cuda_runtime.h>
#include <math.h>

#define BATCH 2048
#define T 50
#define D 256
#define NEGC (-100000.0f)
#define INV_SQRT_D 0.0625f

typedef unsigned int u32;

// ---------------- device scratch ----------------
__device__ float g_Aqk[D * D];
__device__ float g_u[D];
__device__ float g_qrs[D];
__device__ float g_wv[D];
__device__ float g_ksum[D];
__device__ float g_scal[3];
__device__ float g_Z[BATCH * D];
__device__ float g_Yp[2 * BATCH * D];   // split-K partials of Y (z=2)
__device__ float g_Op[2 * BATCH * D];   // split-K partials of out (z=2)

// ---------------- helpers ----------------
__device__ __forceinline__ float dot4(float4 a, float4 b) {
    return a.x * b.x + a.y * b.y + a.z * b.z + a.w * b.w;
}
__device__ __forceinline__ u32 tf32_of(float v) {
    u32 r;
    asm("cvt.rna.tf32.f32 %0, %1;" : "=r"(r) : "f"(v));
    return r;
}
__device__ __forceinline__ void mma_tf32(float c[4], u32 a0, u32 a1, u32 a2, u32 a3,
                                         u32 b0, u32 b1) {
    asm("mma.sync.aligned.m16n8k8.row.col.f32.tf32.tf32.f32 "
        "{%0,%1,%2,%3},{%4,%5,%6,%7},{%8,%9},{%0,%1,%2,%3};"
        : "+f"(c[0]), "+f"(c[1]), "+f"(c[2]), "+f"(c[3])
        : "r"(a0), "r"(a1), "r"(a2), "r"(a3), "r"(b0), "r"(b1));
}

// ---------------- K1: prep (Aqk + small vectors), grid 16x16 ----------------
__global__ __launch_bounds__(256) void prep_kernel(const float* __restrict__ Wq,
                                                   const float* __restrict__ bq,
                                                   const float* __restrict__ Wk,
                                                   const float* __restrict__ bk) {
    __shared__ __align__(16) float Aw[256 * 16];
    __shared__ __align__(16) float Bw[256 * 16];
    __shared__ float s_bq[256], s_bk[256];
    int tid = threadIdx.x;
    int tx = tid & 15, ty = tid >> 4;
    int m0 = blockIdx.y * 16, n0 = blockIdx.x * 16;

    int e0 = tid >> 2, q = tid & 3;
    #pragma unroll
    for (int j = 0; j < 4; j++) {
        int e = e0 + 64 * j;
        float4 a = *(const float4*)(Wq + (size_t)e * D + m0 + q * 4);
        float4 b = *(const float4*)(Wk + (size_t)e * D + n0 + q * 4);
        *(float4*)&Aw[e * 16 + q * 4] = a;
        *(float4*)&Bw[e * 16 + q * 4] = b;
    }
    s_bq[tid] = bq[tid];
    s_bk[tid] = bk[tid];
    __syncthreads();

    float acc = 0.f;
    #pragma unroll 8
    for (int e = 0; e < 256; e++) acc += Aw[e * 16 + ty] * Bw[e * 16 + tx];
    g_Aqk[(m0 + ty) * D + n0 + tx] = acc;

    if (blockIdx.x == 0 && ty == 0) {
        float su = 0.f, sq = 0.f;
        #pragma unroll 8
        for (int e = 0; e < 256; e++) {
            float w = Aw[e * 16 + tx];
            su += s_bk[e] * w;
            sq += w;
        }
        g_u[m0 + tx] = su;
        g_qrs[m0 + tx] = sq;
    }
    if (blockIdx.y == 0 && ty == 1) {
        float sw = 0.f, sk = 0.f;
        #pragma unroll 8
        for (int e = 0; e < 256; e++) {
            float w = Bw[e * 16 + tx];
            sw += s_bq[e] * w;
            sk += w;
        }
        g_wv[n0 + tx] = sw;
        g_ksum[n0 + tx] = sk;
    }
    if (blockIdx.x == 0 && blockIdx.y == 0 && tid < 32) {
        float a0 = 0.f, a1 = 0.f, a2 = 0.f;
        #pragma unroll
        for (int j = 0; j < 8; j++) {
            float qv = s_bq[tid + 32 * j], kv = s_bk[tid + 32 * j];
            a0 += qv * kv; a1 += qv; a2 += kv;
        }
        #pragma unroll
        for (int o = 16; o > 0; o >>= 1) {
            a0 += __shfl_xor_sync(0xffffffffu, a0, o);
            a1 += __shfl_xor_sync(0xffffffffu, a1, o);
            a2 += __shfl_xor_sync(0xffffffffu, a2, o);
        }
        if (tid == 0) { g_scal[0] = a0; g_scal[1] = a1; g_scal[2] = a2; }
    }
}

// ---------------- tensor-core split-K GEMM: 64m x 64n x 128k per CTA ----------------
// grid (4, 32, 2).  3xTF32 via hi/lo split.  Fragment-layout smem.
// ASRC: 0 = x last rows * td    1 = g_Z
// BSRC: 0 = g_Aqk (B[k][n])    1 = Bp NT (B[k][n] = Bp[n][k])
// PDST: 0 = g_Yp               1 = g_Op
template <int ASRC, int BSRC, int PDST>
__global__ __launch_bounds__(256) void gemm_tc(const float* __restrict__ x,
                                               const float* __restrict__ td,
                                               const float* __restrict__ Bp) {
    // AsF: [2 hi/lo][4 kt][4 mt][32 lane][4 aidx]  = 4096 floats (16KB)
    // BsF: [2 hi/lo][4 kt][8 nt][32 lane][2 bidx]  = 4096 floats (16KB)
    __shared__ __align__(16) float AsF[4096];
    __shared__ __align__(16) float BsF[4096];
    const int AH = 2048, BH = 2048;

    int tid = threadIdx.x;
    int n0 = blockIdx.x * 64, m0 = blockIdx.y * 64, ks0 = blockIdx.z * 128;
    int lane = tid & 31, w = tid >> 5, wm = w >> 1, wn = w & 1;

    float c[4][4] = {};  // [nt_local][c-frag]

    // A fill mapping: row r (0..63), k-chunk kq (0,8,16,24)
    int r = tid & 63, kq = (tid >> 6) * 8;
    const float* arow;
    float asc = 1.0f;
    if (ASRC == 0) {
        int gb = m0 + r;
        arow = x + ((size_t)gb * T + (T - 1)) * D;
        asc = td[gb * T + (T - 1)];
    } else {
        arow = g_Z + (size_t)(m0 + r) * D;
    }
    int nn = tid & 63;  // B col for fill

    for (int st = 0; st < 4; st++) {
        int ks = ks0 + st * 32;
        // ---- global loads (overlap previous compute) ----
        float4 a0v = *(const float4*)(arow + ks + kq);
        float4 a1v = *(const float4*)(arow + ks + kq + 4);
        float avv[8] = {a0v.x, a0v.y, a0v.z, a0v.w, a1v.x, a1v.y, a1v.z, a1v.w};
        float bvv[8];
        if (BSRC == 0) {
            #pragma unroll
            for (int i = 0; i < 8; i++)
                bvv[i] = g_Aqk[(size_t)(ks + kq + i) * D + n0 + nn];
        } else {
            const float* brow = Bp + (size_t)(n0 + nn) * D + ks + kq;
            float4 b0v = *(const float4*)brow;
            float4 b1v = *(const float4*)(brow + 4);
            bvv[0] = b0v.x; bvv[1] = b0v.y; bvv[2] = b0v.z; bvv[3] = b0v.w;
            bvv[4] = b1v.x; bvv[5] = b1v.y; bvv[6] = b1v.z; bvv[7] = b1v.w;
        }
        __syncthreads();  // prior compute done before overwrite
        // ---- A scatter into fragment layout ----
        {
            int g = r & 7, mh = (r >> 3) & 1, mt = r >> 4;
            #pragma unroll
            for (int i = 0; i < 8; i++) {
                float v = avv[i] * asc;
                u32 hb = tf32_of(v);
                float lof = v - __uint_as_float(hb);
                u32 lb = tf32_of(lof);
                int kk = kq + i;
                int kt = kk >> 3, cc = kk & 7;
                int tig = cc & 3, ch = cc >> 2;
                int aidx = mh + 2 * ch;
                int ln = g * 4 + tig;
                int base = (((kt * 4 + mt) * 32 + ln) * 4) + aidx;
                AsF[base] = __uint_as_float(hb);
                AsF[AH + base] = __uint_as_float(lb);
            }
        }
        // ---- B scatter ----
        {
            int g2 = nn & 7, nt = nn >> 3;
            #pragma unroll
            for (int i = 0; i < 8; i++) {
                float v = bvv[i];
                u32 hb = tf32_of(v);
                float lof = v - __uint_as_float(hb);
                u32 lb = tf32_of(lof);
                int kk = kq + i;
                int kt = kk >> 3, tr = kk & 7;
                int t = tr & 3, bh = tr >> 2;
                int ln = g2 * 4 + t;
                int base = (((kt * 8 + nt) * 32 + ln) * 2) + bh;
                BsF[base] = __uint_as_float(hb);
                BsF[BH + base] = __uint_as_float(lb);
            }
        }
        __syncthreads();
        // ---- tensor-core compute: 4 k-steps x 4 n-tiles x 3 MMAs ----
        #pragma unroll
        for (int kt = 0; kt < 4; kt++) {
            int abase = ((kt * 4 + wm) * 32 + lane) * 4;
            float4 ah4 = *(const float4*)&AsF[abase];
            float4 al4 = *(const float4*)&AsF[AH + abase];
            u32 ah[4] = {__float_as_uint(ah4.x), __float_as_uint(ah4.y),
                         __float_as_uint(ah4.z), __float_as_uint(ah4.w)};
            u32 al[4] = {__float_as_uint(al4.x), __float_as_uint(al4.y),
                         __float_as_uint(al4.z), __float_as_uint(al4.w)};
            #pragma unroll
            for (int j = 0; j < 4; j++) {
                int nt = wn * 4 + j;
                int bbase = ((kt * 8 + nt) * 32 + lane) * 2;
                float2 bh2 = *(const float2*)&BsF[bbase];
                float2 bl2 = *(const float2*)&BsF[BH + bbase];
                u32 b0h = __float_as_uint(bh2.x), b1h = __float_as_uint(bh2.y);
                u32 b0l = __float_as_uint(bl2.x), b1l = __float_as_uint(bl2.y);
                mma_tf32(c[j], ah[0], ah[1], ah[2], ah[3], b0l, b1l);
                mma_tf32(c[j], al[0], al[1], al[2], al[3], b0h, b1h);
                mma_tf32(c[j], ah[0], ah[1], ah[2], ah[3], b0h, b1h);
            }
        }
    }

    // ---- epilogue: write partial tile ----
    float* part = (PDST == 0) ? g_Yp : g_Op;
    int g = lane >> 2, t = lane & 3;
    int gm = m0 + wm * 16 + g;
    #pragma unroll
    for (int j = 0; j < 4; j++) {
        int nt = wn * 4 + j;
        int gn = n0 + nt * 8 + 2 * t;
        size_t base = ((size_t)blockIdx.z * BATCH + gm) * D + gn;
        *(float2*)&part[base] = make_float2(c[j][0], c[j][1]);
        *(float2*)&part[base + (size_t)8 * D] = make_float2(c[j][2], c[j][3]);
    }
}

// ---------------- K3: attn ----------------
__global__ __launch_bounds__(256, 4) void attn_kernel(const float* __restrict__ x,
                                                      const int* __restrict__ mask,
                                                      const float* __restrict__ td) {
    extern __shared__ float sm[];
    float* smx = sm;                 // 50*256
    float* smV = sm + T * D;         // 256
    float* smtd = smV + D;           // 64
    float* smDV = smtd + 64;         // 64 (50,51 hold dU,dQ)
    float* smw = smDV + 64;          // 64
    int* smm = (int*)(smw + 64);     // 64

    int b = blockIdx.x, tid = threadIdx.x;
    int warp = tid >> 5, lane = tid & 31;

    int mq = __ldg(mask + b * T + (T - 1));
    const float4* xin4 = (const float4*)(x + (size_t)b * T * D);
    float4* smx4 = (float4*)smx;
    #pragma unroll
    for (int i = tid; i < T * D / 4; i += 256) smx4[i] = xin4[i];
    if (mq) {
        int idx = b * D + tid;
        smV[tid] = g_Yp[idx] + g_Yp[BATCH * D + idx] + g_wv[tid];
    } else {
        smV[tid] = g_ksum[tid];
    }
    if (tid < T) {
        smtd[tid] = td[b * T + tid];
        smm[tid] = mask[b * T + tid];
    }
    __syncthreads();

    float4 va = ((const float4*)smV)[lane];
    float4 vb = ((const float4*)smV)[lane + 32];
    for (int s = warp; s < T; s += 8) {
        float4 x1 = smx4[s * 64 + lane];
        float4 x2 = smx4[s * 64 + 32 + lane];
        float dv = dot4(x1, va) + dot4(x2, vb);
        #pragma unroll
        for (int o = 16; o > 0; o >>= 1) dv += __shfl_xor_sync(0xffffffffu, dv, o);
        if (lane == 0) smDV[s] = dv;
    }
    if (warp == 2 || warp == 3) {
        const float4* w4 = (warp == 2) ? (const float4*)g_u : (const float4*)g_qrs;
        float4 x1 = smx4[(T - 1) * 64 + lane];
        float4 x2 = smx4[(T - 1) * 64 + 32 + lane];
        float dv = dot4(x1, __ldg(w4 + lane)) + dot4(x2, __ldg(w4 + lane + 32));
        #pragma unroll
        for (int o = 16; o > 0; o >>= 1) dv += __shfl_xor_sync(0xffffffffu, dv, o);
        if (lane == 0) smDV[T + (warp - 2)] = dv;
    }
    __syncthreads();

    if (warp == 0) {
        float tdl = smtd[T - 1];
        float s1b = tdl * smDV[T] + g_scal[0];
        float s2b = tdl * smDV[T + 1] + g_scal[1];
        float bksum = g_scal[2];
        float v1 = -3.0e38f, v2 = -3.0e38f;
        if (lane < T) {
            int ms = smm[lane];
            float tds = smtd[lane];
            if (mq) v1 = ms ? (tds * smDV[lane] + s1b) : (NEGC * s2b);
            else    v1 = ms ? (NEGC * (tds * smDV[lane] + bksum)) : (NEGC * NEGC * (float)D);
            v1 *= INV_SQRT_D;
        }
        if (lane + 32 < T) {
            int s = lane + 32;
            int ms = smm[s];
            float tds = smtd[s];
            if (mq) v2 = ms ? (tds * smDV[s] + s1b) : (NEGC * s2b);
            else    v2 = ms ? (NEGC * (tds * smDV[s] + bksum)) : (NEGC * NEGC * (float)D);
            v2 *= INV_SQRT_D;
        }
        float m = fmaxf(v1, v2);
        #pragma unroll
        for (int o = 16; o > 0; o >>= 1) m = fmaxf(m, __shfl_xor_sync(0xffffffffu, m, o));
        float e1 = (lane < T) ? expf(v1 - m) : 0.f;
        float e2 = (lane + 32 < T) ? expf(v2 - m) : 0.f;
        float es = e1 + e2;
        #pragma unroll
        for (int o = 16; o > 0; o >>= 1) es += __shfl_xor_sync(0xffffffffu, es, o);
        float inv = 1.0f / es;
        if (lane < T) smw[lane] = e1 * inv * smtd[lane];
        if (lane + 32 < T) smw[lane + 32] = e2 * inv * smtd[lane + 32];
    }
    __syncthreads();

    int g = tid >> 6, q = tid & 63;
    float4 acc = make_float4(0.f, 0.f, 0.f, 0.f);
    for (int s = g; s < T; s += 4) {
        float w = smw[s];
        float4 xv = smx4[s * 64 + q];
        acc.x += w * xv.x; acc.y += w * xv.y; acc.z += w * xv.z; acc.w += w * xv.w;
    }
    __syncthreads();
    smx4[g * 64 + q] = acc;
    __syncthreads();
    if (tid < 64) {
        float4 p0 = smx4[tid], p1 = smx4[64 + tid];
        float4 p2 = smx4[128 + tid], p3 = smx4[192 + tid];
        float4 r = make_float4(p0.x + p1.x + p2.x + p3.x, p0.y + p1.y + p2.y + p3.y,
                               p0.z + p1.z + p2.z + p3.z, p0.w + p1.w + p2.w + p3.w);
        ((float4*)(g_Z + (size_t)b * D))[tid] = r;
    }
}

// ---------------- K5: reduce out partials + bias ----------------
__global__ __launch_bounds__(256) void reduce_out(const float* __restrict__ bv,
                                                  float* __restrict__ out) {
    int i = blockIdx.x * 256 + threadIdx.x;
    const float4* p = (const float4*)g_Op;
    const int Q = BATCH * D / 4;
    float4 a = p[i], b = p[i + Q];
    float4 bb = ((const float4*)bv)[i & 63];
    float4 r = make_float4(a.x + b.x + bb.x, a.y + b.y + bb.y,
                           a.z + b.z + bb.z, a.w + b.w + bb.w);
    ((float4*)out)[i] = r;
}

// ---------------- launch ----------------
extern "C" void kernel_launch(void* const* d_in, const int* in_sizes, int n_in,
                              void* d_out, int out_size) {
    const float* x = (const float*)d_in[0];
    const int* mask = (const int*)d_in[1];
    const float* td = (const float*)d_in[2];
    const float* Wq = (const float*)d_in[3];
    const float* bq = (const float*)d_in[4];
    const float* Wk = (const float*)d_in[5];
    const float* bk = (const float*)d_in[6];
    const float* Wv = (const float*)d_in[7];
    const float* bv = (const float*)d_in[8];
    float* out = (float*)d_out;

    const int attn_smem = (T * D + D + 64 + 64 + 64 + 64) * 4;  // 53.25 KB
    cudaFuncSetAttribute(attn_kernel, cudaFuncAttributeMaxDynamicSharedMemorySize, attn_smem);

    dim3 gtc(4, 32, 2);
    prep_kernel<<<dim3(16, 16), 256>>>(Wq, bq, Wk, bk);
    gemm_tc<0, 0, 0><<<gtc, 256>>>(x, td, nullptr);        // Y partials
    attn_kernel<<<BATCH, 256, attn_smem>>>(x, mask, td);
    gemm_tc<1, 1, 1><<<gtc, 256>>>(nullptr, nullptr, Wv);  // out partials
    reduce_out<<<BATCH * D / 4 / 256, 256>>>(bv, out);
}

// round 9
// speedup vs baseline: 1.1070x; 1.1070x over previous
#include <cuda_runtime.h>
#include <math.h>

#define BATCH 2048
#define HB 1024
#define T 50
#define D 256
#define NEGC (-100000.0f)
#define INV_SQRT_D 0.0625f

typedef unsigned long long u64;

// ---------------- device scratch ----------------
__device__ float g_Aqk[D * D];
__device__ float g_u[D];
__device__ float g_qrs[D];
__device__ float g_wv[D];
__device__ float g_ksum[D];
__device__ float g_scal[3];
__device__ float g_Z[BATCH * D];
__device__ float g_Yp[4 * BATCH * D];   // split-K partials of Y
__device__ float g_Op[4 * BATCH * D];   // split-K partials of out

// ---------------- stream/event infra (created at load, before capture) ----------------
namespace {
struct Infra {
    cudaStream_t s1;
    cudaEvent_t ev[4];
    Infra() {
        cudaStreamCreateWithFlags(&s1, cudaStreamNonBlocking);
        for (int i = 0; i < 4; i++) cudaEventCreateWithFlags(&ev[i], cudaEventDisableTiming);
    }
};
Infra g_infra;
}

// ---------------- f32x2 helpers ----------------
__device__ __forceinline__ void ffma2(u64& d, u64 a, u64 b) {
    asm("fma.rn.f32x2 %0, %1, %2, %0;" : "+l"(d) : "l"(a), "l"(b));
}
__device__ __forceinline__ float2 unpack2(u64 v) {
    float2 r;
    asm("mov.b64 {%0, %1}, %2;" : "=f"(r.x), "=f"(r.y) : "l"(v));
    return r;
}
__device__ __forceinline__ u64 pack_dup(float v) {
    u64 r;
    asm("mov.b64 %0, {%1, %1};" : "=l"(r) : "f"(v));
    return r;
}
__device__ __forceinline__ float dot4(float4 a, float4 b) {
    return a.x * b.x + a.y * b.y + a.z * b.z + a.w * b.w;
}

// ---------------- K1: prep (Aqk + small vectors), grid 16x16 ----------------
__global__ __launch_bounds__(256) void prep_kernel(const float* __restrict__ Wq,
                                                   const float* __restrict__ bq,
                                                   const float* __restrict__ Wk,
                                                   const float* __restrict__ bk) {
    __shared__ __align__(16) float Aw[256 * 16];
    __shared__ __align__(16) float Bw[256 * 16];
    __shared__ float s_bq[256], s_bk[256];
    int tid = threadIdx.x;
    int tx = tid & 15, ty = tid >> 4;
    int m0 = blockIdx.y * 16, n0 = blockIdx.x * 16;

    int e0 = tid >> 2, q = tid & 3;
    #pragma unroll
    for (int j = 0; j < 4; j++) {
        int e = e0 + 64 * j;
        float4 a = *(const float4*)(Wq + (size_t)e * D + m0 + q * 4);
        float4 b = *(const float4*)(Wk + (size_t)e * D + n0 + q * 4);
        *(float4*)&Aw[e * 16 + q * 4] = a;
        *(float4*)&Bw[e * 16 + q * 4] = b;
    }
    s_bq[tid] = bq[tid];
    s_bk[tid] = bk[tid];
    __syncthreads();

    float acc = 0.f;
    #pragma unroll 8
    for (int e = 0; e < 256; e++) acc += Aw[e * 16 + ty] * Bw[e * 16 + tx];
    g_Aqk[(m0 + ty) * D + n0 + tx] = acc;

    if (blockIdx.x == 0 && ty == 0) {
        float su = 0.f, sq = 0.f;
        #pragma unroll 8
        for (int e = 0; e < 256; e++) {
            float w = Aw[e * 16 + tx];
            su += s_bk[e] * w;
            sq += w;
        }
        g_u[m0 + tx] = su;
        g_qrs[m0 + tx] = sq;
    }
    if (blockIdx.y == 0 && ty == 1) {
        float sw = 0.f, sk = 0.f;
        #pragma unroll 8
        for (int e = 0; e < 256; e++) {
            float w = Bw[e * 16 + tx];
            sw += s_bq[e] * w;
            sk += w;
        }
        g_wv[n0 + tx] = sw;
        g_ksum[n0 + tx] = sk;
    }
    if (blockIdx.x == 0 && blockIdx.y == 0 && tid < 32) {
        float a0 = 0.f, a1 = 0.f, a2 = 0.f;
        #pragma unroll
        for (int j = 0; j < 8; j++) {
            float qv = s_bq[tid + 32 * j], kv = s_bk[tid + 32 * j];
            a0 += qv * kv; a1 += qv; a2 += kv;
        }
        #pragma unroll
        for (int o = 16; o > 0; o >>= 1) {
            a0 += __shfl_xor_sync(0xffffffffu, a0, o);
            a1 += __shfl_xor_sync(0xffffffffu, a1, o);
            a2 += __shfl_xor_sync(0xffffffffu, a2, o);
        }
        if (tid == 0) { g_scal[0] = a0; g_scal[1] = a1; g_scal[2] = a2; }
    }
}

// ---------------- split-K GEMM: 128m x 64n x 64k per CTA, grid (4,8,4) per chunk ----------------
// ASRC: 0 = x last rows * td    1 = g_Z
// BSRC: 0 = g_Aqk (NN)         1 = param B (NT, B[n][k])
// PDST: 0 = g_Yp               1 = g_Op
template <int ASRC, int BSRC, int PDST>
__global__ __launch_bounds__(256) void gemm_sk(const float* __restrict__ x,
                                               const float* __restrict__ td,
                                               const float* __restrict__ Bp, int mbase) {
    __shared__ __align__(16) float As[64 * 128];  // [k][m] 32KB
    __shared__ __align__(16) float Bs[64 * 64];   // [k][n] 16KB
    int tid = threadIdx.x;
    int n0 = blockIdx.x * 64, m0 = mbase + blockIdx.y * 128, ks = blockIdx.z * 64;

    // ---- A fill ----
    {
        int r = tid & 127, kc = (tid >> 7) * 32;
        const float* arow;
        float asc = 1.0f;
        if (ASRC == 0) {
            int gb = m0 + r;
            arow = x + ((size_t)gb * T + (T - 1)) * D;
            asc = td[gb * T + (T - 1)];
        } else {
            arow = g_Z + (size_t)(m0 + r) * D;
        }
        float4 v[8];
        #pragma unroll
        for (int i = 0; i < 8; i++) v[i] = *(const float4*)(arow + ks + kc + i * 4);
        #pragma unroll
        for (int i = 0; i < 8; i++) {
            As[(kc + i * 4 + 0) * 128 + r] = v[i].x * asc;
            As[(kc + i * 4 + 1) * 128 + r] = v[i].y * asc;
            As[(kc + i * 4 + 2) * 128 + r] = v[i].z * asc;
            As[(kc + i * 4 + 3) * 128 + r] = v[i].w * asc;
        }
    }
    // ---- B fill ----
    if (BSRC == 0) {
        int q = tid & 15, kr0 = tid >> 4;
        #pragma unroll
        for (int p = 0; p < 4; p++) {
            int kr = kr0 + p * 16;
            float4 v = *(const float4*)(g_Aqk + (size_t)(ks + kr) * D + n0 + q * 4);
            *(float4*)&Bs[kr * 64 + q * 4] = v;
        }
    } else {
        int nr = tid & 63, kq = (tid >> 6) * 16;
        const float* brow = Bp + (size_t)(n0 + nr) * D + ks + kq;
        float4 v0 = *(const float4*)(brow);
        float4 v1 = *(const float4*)(brow + 4);
        float4 v2 = *(const float4*)(brow + 8);
        float4 v3 = *(const float4*)(brow + 12);
        float vs[16] = {v0.x, v0.y, v0.z, v0.w, v1.x, v1.y, v1.z, v1.w,
                        v2.x, v2.y, v2.z, v2.w, v3.x, v3.y, v3.z, v3.w};
        #pragma unroll
        for (int i = 0; i < 16; i++) Bs[(kq + i) * 64 + nr] = vs[i];
    }
    __syncthreads();

    // ---- inner loop: thread tile 8m x 4n, f32x2 over m-pairs ----
    int tx = tid & 15, ty = tid >> 4;
    u64 acc[4][4] = {};
    #pragma unroll 2
    for (int kk = 0; kk < 64; kk += 16) {
        #pragma unroll
        for (int k2 = 0; k2 < 16; k2++) {
            int k = kk + k2;
            ulonglong2 a01 = *(const ulonglong2*)&As[k * 128 + ty * 8];
            ulonglong2 a23 = *(const ulonglong2*)&As[k * 128 + ty * 8 + 4];
            float4 b4 = *(const float4*)&Bs[k * 64 + tx * 4];
            u64 b0 = pack_dup(b4.x), b1 = pack_dup(b4.y);
            u64 b2 = pack_dup(b4.z), b3 = pack_dup(b4.w);
            ffma2(acc[0][0], a01.x, b0); ffma2(acc[0][1], a01.x, b1);
            ffma2(acc[0][2], a01.x, b2); ffma2(acc[0][3], a01.x, b3);
            ffma2(acc[1][0], a01.y, b0); ffma2(acc[1][1], a01.y, b1);
            ffma2(acc[1][2], a01.y, b2); ffma2(acc[1][3], a01.y, b3);
            ffma2(acc[2][0], a23.x, b0); ffma2(acc[2][1], a23.x, b1);
            ffma2(acc[2][2], a23.x, b2); ffma2(acc[2][3], a23.x, b3);
            ffma2(acc[3][0], a23.y, b0); ffma2(acc[3][1], a23.y, b1);
            ffma2(acc[3][2], a23.y, b2); ffma2(acc[3][3], a23.y, b3);
        }
    }

    // ---- write partial tile ----
    float* part = (PDST == 0) ? g_Yp : g_Op;
    int gn = n0 + tx * 4;
    int gmb = m0 + ty * 8;
    size_t base = ((size_t)blockIdx.z * BATCH + gmb) * D + gn;
    #pragma unroll
    for (int mp = 0; mp < 4; mp++) {
        float2 p0 = unpack2(acc[mp][0]), p1 = unpack2(acc[mp][1]);
        float2 p2 = unpack2(acc[mp][2]), p3 = unpack2(acc[mp][3]);
        *(float4*)&part[base + (size_t)(2 * mp) * D] = make_float4(p0.x, p1.x, p2.x, p3.x);
        *(float4*)&part[base + (size_t)(2 * mp + 1) * D] = make_float4(p0.y, p1.y, p2.y, p3.y);
    }
}

// ---------------- K3: attn (per-chunk) ----------------
__global__ __launch_bounds__(256, 4) void attn_kernel(const float* __restrict__ x,
                                                      const int* __restrict__ mask,
                                                      const float* __restrict__ td, int bbase) {
    extern __shared__ float sm[];
    float* smx = sm;                 // 50*256
    float* smV = sm + T * D;         // 256
    float* smtd = smV + D;           // 64
    float* smDV = smtd + 64;         // 64 (50,51 hold dU,dQ)
    float* smw = smDV + 64;          // 64
    int* smm = (int*)(smw + 64);     // 64

    int b = bbase + blockIdx.x, tid = threadIdx.x;
    int warp = tid >> 5, lane = tid & 31;

    int mq = __ldg(mask + b * T + (T - 1));
    const float4* xin4 = (const float4*)(x + (size_t)b * T * D);
    float4* smx4 = (float4*)smx;
    #pragma unroll
    for (int i = tid; i < T * D / 4; i += 256) smx4[i] = xin4[i];
    if (mq) {
        int idx = b * D + tid;
        smV[tid] = g_Yp[idx] + g_Yp[BATCH * D + idx] + g_Yp[2 * BATCH * D + idx] +
                   g_Yp[3 * BATCH * D + idx] + g_wv[tid];
    } else {
        smV[tid] = g_ksum[tid];
    }
    if (tid < T) {
        smtd[tid] = td[b * T + tid];
        smm[tid] = mask[b * T + tid];
    }
    __syncthreads();

    float4 va = ((const float4*)smV)[lane];
    float4 vb = ((const float4*)smV)[lane + 32];
    for (int s = warp; s < T; s += 8) {
        float4 x1 = smx4[s * 64 + lane];
        float4 x2 = smx4[s * 64 + 32 + lane];
        float dv = dot4(x1, va) + dot4(x2, vb);
        #pragma unroll
        for (int o = 16; o > 0; o >>= 1) dv += __shfl_xor_sync(0xffffffffu, dv, o);
        if (lane == 0) smDV[s] = dv;
    }
    if (warp == 2 || warp == 3) {
        const float4* w4 = (warp == 2) ? (const float4*)g_u : (const float4*)g_qrs;
        float4 x1 = smx4[(T - 1) * 64 + lane];
        float4 x2 = smx4[(T - 1) * 64 + 32 + lane];
        float dv = dot4(x1, __ldg(w4 + lane)) + dot4(x2, __ldg(w4 + lane + 32));
        #pragma unroll
        for (int o = 16; o > 0; o >>= 1) dv += __shfl_xor_sync(0xffffffffu, dv, o);
        if (lane == 0) smDV[T + (warp - 2)] = dv;
    }
    __syncthreads();

    if (warp == 0) {
        float tdl = smtd[T - 1];
        float s1b = tdl * smDV[T] + g_scal[0];
        float s2b = tdl * smDV[T + 1] + g_scal[1];
        float bksum = g_scal[2];
        float v1 = -3.0e38f, v2 = -3.0e38f;
        if (lane < T) {
            int ms = smm[lane];
            float tds = smtd[lane];
            if (mq) v1 = ms ? (tds * smDV[lane] + s1b) : (NEGC * s2b);
            else    v1 = ms ? (NEGC * (tds * smDV[lane] + bksum)) : (NEGC * NEGC * (float)D);
            v1 *= INV_SQRT_D;
        }
        if (lane + 32 < T) {
            int s = lane + 32;
            int ms = smm[s];
            float tds = smtd[s];
            if (mq) v2 = ms ? (tds * smDV[s] + s1b) : (NEGC * s2b);
            else    v2 = ms ? (NEGC * (tds * smDV[s] + bksum)) : (NEGC * NEGC * (float)D);
            v2 *= INV_SQRT_D;
        }
        float m = fmaxf(v1, v2);
        #pragma unroll
        for (int o = 16; o > 0; o >>= 1) m = fmaxf(m, __shfl_xor_sync(0xffffffffu, m, o));
        float e1 = (lane < T) ? expf(v1 - m) : 0.f;
        float e2 = (lane + 32 < T) ? expf(v2 - m) : 0.f;
        float es = e1 + e2;
        #pragma unroll
        for (int o = 16; o > 0; o >>= 1) es += __shfl_xor_sync(0xffffffffu, es, o);
        float inv = 1.0f / es;
        if (lane < T) smw[lane] = e1 * inv * smtd[lane];
        if (lane + 32 < T) smw[lane + 32] = e2 * inv * smtd[lane + 32];
    }
    __syncthreads();

    int g = tid >> 6, q = tid & 63;
    float4 acc = make_float4(0.f, 0.f, 0.f, 0.f);
    for (int s = g; s < T; s += 4) {
        float w = smw[s];
        float4 xv = smx4[s * 64 + q];
        acc.x += w * xv.x; acc.y += w * xv.y; acc.z += w * xv.z; acc.w += w * xv.w;
    }
    __syncthreads();
    smx4[g * 64 + q] = acc;
    __syncthreads();
    if (tid < 64) {
        float4 p0 = smx4[tid], p1 = smx4[64 + tid];
        float4 p2 = smx4[128 + tid], p3 = smx4[192 + tid];
        float4 r = make_float4(p0.x + p1.x + p2.x + p3.x, p0.y + p1.y + p2.y + p3.y,
                               p0.z + p1.z + p2.z + p3.z, p0.w + p1.w + p2.w + p3.w);
        ((float4*)(g_Z + (size_t)b * D))[tid] = r;
    }
}

// ---------------- K5: reduce out partials + bias (per-chunk) ----------------
__global__ __launch_bounds__(256) void reduce_out(const float* __restrict__ bv,
                                                  float* __restrict__ out, int i0) {
    int i = i0 + blockIdx.x * 256 + threadIdx.x;
    const float4* p = (const float4*)g_Op;
    const int Q = BATCH * D / 4;
    float4 a = p[i], b = p[i + Q], c = p[i + 2 * Q], d = p[i + 3 * Q];
    float4 bb = ((const float4*)bv)[i & 63];
    float4 r = make_float4(a.x + b.x + c.x + d.x + bb.x, a.y + b.y + c.y + d.y + bb.y,
                           a.z + b.z + c.z + d.z + bb.z, a.w + b.w + c.w + d.w + bb.w);
    ((float4*)out)[i] = r;
}

// ---------------- launch: 2-stream chunked pipeline ----------------
extern "C" void kernel_launch(void* const* d_in, const int* in_sizes, int n_in,
                              void* d_out, int out_size) {
    const float* x = (const float*)d_in[0];
    const int* mask = (const int*)d_in[1];
    const float* td = (const float*)d_in[2];
    const float* Wq = (const float*)d_in[3];
    const float* bq = (const float*)d_in[4];
    const float* Wk = (const float*)d_in[5];
    const float* bk = (const float*)d_in[6];
    const float* Wv = (const float*)d_in[7];
    const float* bv = (const float*)d_in[8];
    float* out = (float*)d_out;

    const int attn_smem = (T * D + D + 64 + 64 + 64 + 64) * 4;  // 53.25 KB
    cudaFuncSetAttribute(attn_kernel, cudaFuncAttributeMaxDynamicSharedMemorySize, attn_smem);

    cudaStream_t s1 = g_infra.s1;
    dim3 gsk(4, 8, 4);
    const int RQ = HB * D / 4 / 256;  // reduce blocks per chunk

    // stream 0: prep, Y-GEMMs
    prep_kernel<<<dim3(16, 16), 256>>>(Wq, bq, Wk, bk);
    gemm_sk<0, 0, 0><<<gsk, 256>>>(x, td, nullptr, 0);
    cudaEventRecord(g_infra.ev[0], 0);
    gemm_sk<0, 0, 0><<<gsk, 256>>>(x, td, nullptr, HB);
    cudaEventRecord(g_infra.ev[1], 0);

    // stream 1: attn chunks (each waits on its Y chunk)
    cudaStreamWaitEvent(s1, g_infra.ev[0], 0);
    attn_kernel<<<HB, 256, attn_smem, s1>>>(x, mask, td, 0);
    cudaEventRecord(g_infra.ev[2], s1);
    cudaStreamWaitEvent(s1, g_infra.ev[1], 0);
    attn_kernel<<<HB, 256, attn_smem, s1>>>(x, mask, td, HB);
    cudaEventRecord(g_infra.ev[3], s1);

    // stream 0: out-GEMMs + reduces (each waits on its attn chunk)
    cudaStreamWaitEvent(0, g_infra.ev[2], 0);
    gemm_sk<1, 1, 1><<<gsk, 256>>>(nullptr, nullptr, Wv, 0);
    reduce_out<<<RQ, 256>>>(bv, out, 0);
    cudaStreamWaitEvent(0, g_infra.ev[3], 0);
    gemm_sk<1, 1, 1><<<gsk, 256>>>(nullptr, nullptr, Wv, HB);
    reduce_out<<<RQ, 256>>>(bv, out, HB * D / 4);
}

// round 10
// speedup vs baseline: 1.3633x; 1.2315x over previous
#include <cuda_runtime.h>
#include <math.h>

#define BATCH 2048
#define T 50
#define D 256
#define NEGC (-100000.0f)
#define INV_SQRT_D 0.0625f

typedef unsigned long long u64;

// ---------------- device scratch ----------------
__device__ float g_Aqk[D * D];
__device__ float g_u[D];
__device__ float g_qrs[D];
__device__ float g_wv[D];
__device__ float g_ksum[D];
__device__ float g_scal[3];
__device__ float g_Z[BATCH * D];
__device__ float g_Yp[4 * BATCH * D];   // split-K partials of Y
__device__ float g_Op[4 * BATCH * D];   // split-K partials of out

// ---------------- f32x2 helpers ----------------
__device__ __forceinline__ void ffma2(u64& d, u64 a, u64 b) {
    asm("fma.rn.f32x2 %0, %1, %2, %0;" : "+l"(d) : "l"(a), "l"(b));
}
__device__ __forceinline__ float2 unpack2(u64 v) {
    float2 r;
    asm("mov.b64 {%0, %1}, %2;" : "=f"(r.x), "=f"(r.y) : "l"(v));
    return r;
}
__device__ __forceinline__ u64 pack_dup(float v) {
    u64 r;
    asm("mov.b64 %0, {%1, %1};" : "=l"(r) : "f"(v));
    return r;
}
__device__ __forceinline__ float dot4(float4 a, float4 b) {
    return a.x * b.x + a.y * b.y + a.z * b.z + a.w * b.w;
}
__device__ __forceinline__ unsigned smem_u32(const void* p) {
    unsigned a;
    asm("{ .reg .u64 t; cvta.to.shared.u64 t, %1; cvt.u32.u64 %0, t; }" : "=r"(a) : "l"(p));
    return a;
}

// ---------------- K1: prep (Aqk + small vectors), grid 16x16 ----------------
__global__ __launch_bounds__(256) void prep_kernel(const float* __restrict__ Wq,
                                                   const float* __restrict__ bq,
                                                   const float* __restrict__ Wk,
                                                   const float* __restrict__ bk) {
    __shared__ __align__(16) float Aw[256 * 16];
    __shared__ __align__(16) float Bw[256 * 16];
    __shared__ float s_bq[256], s_bk[256];
    int tid = threadIdx.x;
    int tx = tid & 15, ty = tid >> 4;
    int m0 = blockIdx.y * 16, n0 = blockIdx.x * 16;

    int e0 = tid >> 2, q = tid & 3;
    #pragma unroll
    for (int j = 0; j < 4; j++) {
        int e = e0 + 64 * j;
        float4 a = *(const float4*)(Wq + (size_t)e * D + m0 + q * 4);
        float4 b = *(const float4*)(Wk + (size_t)e * D + n0 + q * 4);
        *(float4*)&Aw[e * 16 + q * 4] = a;
        *(float4*)&Bw[e * 16 + q * 4] = b;
    }
    s_bq[tid] = bq[tid];
    s_bk[tid] = bk[tid];
    __syncthreads();

    float acc = 0.f;
    #pragma unroll 8
    for (int e = 0; e < 256; e++) acc += Aw[e * 16 + ty] * Bw[e * 16 + tx];
    g_Aqk[(m0 + ty) * D + n0 + tx] = acc;

    if (blockIdx.x == 0 && ty == 0) {
        float su = 0.f, sq = 0.f;
        #pragma unroll 8
        for (int e = 0; e < 256; e++) {
            float w = Aw[e * 16 + tx];
            su += s_bk[e] * w;
            sq += w;
        }
        g_u[m0 + tx] = su;
        g_qrs[m0 + tx] = sq;
    }
    if (blockIdx.y == 0 && ty == 1) {
        float sw = 0.f, sk = 0.f;
        #pragma unroll 8
        for (int e = 0; e < 256; e++) {
            float w = Bw[e * 16 + tx];
            sw += s_bq[e] * w;
            sk += w;
        }
        g_wv[n0 + tx] = sw;
        g_ksum[n0 + tx] = sk;
    }
    if (blockIdx.x == 0 && blockIdx.y == 0 && tid < 32) {
        float a0 = 0.f, a1 = 0.f, a2 = 0.f;
        #pragma unroll
        for (int j = 0; j < 8; j++) {
            float qv = s_bq[tid + 32 * j], kv = s_bk[tid + 32 * j];
            a0 += qv * kv; a1 += qv; a2 += kv;
        }
        #pragma unroll
        for (int o = 16; o > 0; o >>= 1) {
            a0 += __shfl_xor_sync(0xffffffffu, a0, o);
            a1 += __shfl_xor_sync(0xffffffffu, a1, o);
            a2 += __shfl_xor_sync(0xffffffffu, a2, o);
        }
        if (tid == 0) { g_scal[0] = a0; g_scal[1] = a1; g_scal[2] = a2; }
    }
}

// ---------------- split-K GEMM: 128m x 64n x 64k per CTA, grid (4,16,4) ----------------
// ASRC: 0 = x last rows * td    1 = g_Z
// BSRC: 0 = g_Aqk (NN)         1 = param B (NT, B[n][k])
// PDST: 0 = g_Yp               1 = g_Op
template <int ASRC, int BSRC, int PDST>
__global__ __launch_bounds__(256) void gemm_sk(const float* __restrict__ x,
                                               const float* __restrict__ td,
                                               const float* __restrict__ Bp) {
    __shared__ __align__(16) float As[64 * 128];  // [k][m] 32KB
    __shared__ __align__(16) float Bs[64 * 64];   // [k][n] 16KB
    int tid = threadIdx.x;
    int n0 = blockIdx.x * 64, m0 = blockIdx.y * 128, ks = blockIdx.z * 64;

    // ---- A fill ----
    {
        int r = tid & 127, kc = (tid >> 7) * 32;
        const float* arow;
        float asc = 1.0f;
        if (ASRC == 0) {
            int gb = m0 + r;
            arow = x + ((size_t)gb * T + (T - 1)) * D;
            asc = td[gb * T + (T - 1)];
        } else {
            arow = g_Z + (size_t)(m0 + r) * D;
        }
        float4 v[8];
        #pragma unroll
        for (int i = 0; i < 8; i++) v[i] = *(const float4*)(arow + ks + kc + i * 4);
        #pragma unroll
        for (int i = 0; i < 8; i++) {
            As[(kc + i * 4 + 0) * 128 + r] = v[i].x * asc;
            As[(kc + i * 4 + 1) * 128 + r] = v[i].y * asc;
            As[(kc + i * 4 + 2) * 128 + r] = v[i].z * asc;
            As[(kc + i * 4 + 3) * 128 + r] = v[i].w * asc;
        }
    }
    // ---- B fill ----
    if (BSRC == 0) {
        int q = tid & 15, kr0 = tid >> 4;
        #pragma unroll
        for (int p = 0; p < 4; p++) {
            int kr = kr0 + p * 16;
            float4 v = *(const float4*)(g_Aqk + (size_t)(ks + kr) * D + n0 + q * 4);
            *(float4*)&Bs[kr * 64 + q * 4] = v;
        }
    } else {
        int nr = tid & 63, kq = (tid >> 6) * 16;
        const float* brow = Bp + (size_t)(n0 + nr) * D + ks + kq;
        float4 v0 = *(const float4*)(brow);
        float4 v1 = *(const float4*)(brow + 4);
        float4 v2 = *(const float4*)(brow + 8);
        float4 v3 = *(const float4*)(brow + 12);
        float vs[16] = {v0.x, v0.y, v0.z, v0.w, v1.x, v1.y, v1.z, v1.w,
                        v2.x, v2.y, v2.z, v2.w, v3.x, v3.y, v3.z, v3.w};
        #pragma unroll
        for (int i = 0; i < 16; i++) Bs[(kq + i) * 64 + nr] = vs[i];
    }
    __syncthreads();

    // ---- inner loop: thread tile 8m x 4n, f32x2 over m-pairs ----
    int tx = tid & 15, ty = tid >> 4;
    u64 acc[4][4] = {};
    #pragma unroll 2
    for (int kk = 0; kk < 64; kk += 16) {
        #pragma unroll
        for (int k2 = 0; k2 < 16; k2++) {
            int k = kk + k2;
            ulonglong2 a01 = *(const ulonglong2*)&As[k * 128 + ty * 8];
            ulonglong2 a23 = *(const ulonglong2*)&As[k * 128 + ty * 8 + 4];
            float4 b4 = *(const float4*)&Bs[k * 64 + tx * 4];
            u64 b0 = pack_dup(b4.x), b1 = pack_dup(b4.y);
            u64 b2 = pack_dup(b4.z), b3 = pack_dup(b4.w);
            ffma2(acc[0][0], a01.x, b0); ffma2(acc[0][1], a01.x, b1);
            ffma2(acc[0][2], a01.x, b2); ffma2(acc[0][3], a01.x, b3);
            ffma2(acc[1][0], a01.y, b0); ffma2(acc[1][1], a01.y, b1);
            ffma2(acc[1][2], a01.y, b2); ffma2(acc[1][3], a01.y, b3);
            ffma2(acc[2][0], a23.x, b0); ffma2(acc[2][1], a23.x, b1);
            ffma2(acc[2][2], a23.x, b2); ffma2(acc[2][3], a23.x, b3);
            ffma2(acc[3][0], a23.y, b0); ffma2(acc[3][1], a23.y, b1);
            ffma2(acc[3][2], a23.y, b2); ffma2(acc[3][3], a23.y, b3);
        }
    }

    // ---- write partial tile ----
    float* part = (PDST == 0) ? g_Yp : g_Op;
    int gn = n0 + tx * 4;
    int gmb = m0 + ty * 8;
    size_t base = ((size_t)blockIdx.z * BATCH + gmb) * D + gn;
    #pragma unroll
    for (int mp = 0; mp < 4; mp++) {
        float2 p0 = unpack2(acc[mp][0]), p1 = unpack2(acc[mp][1]);
        float2 p2 = unpack2(acc[mp][2]), p3 = unpack2(acc[mp][3]);
        *(float4*)&part[base + (size_t)(2 * mp) * D] = make_float4(p0.x, p1.x, p2.x, p3.x);
        *(float4*)&part[base + (size_t)(2 * mp + 1) * D] = make_float4(p0.y, p1.y, p2.y, p3.y);
    }
}

// ---------------- K3: attn — TMA bulk-copy x tile ----------------
__global__ __launch_bounds__(256, 4) void attn_kernel(const float* __restrict__ x,
                                                      const int* __restrict__ mask,
                                                      const float* __restrict__ td) {
    extern __shared__ __align__(128) float sm[];
    // layout: [0..31] mbar + pad (128B), then x tile, then small arrays
    u64* mbar = (u64*)sm;
    float* smx = sm + 32;            // 50*256 floats, 128B-aligned
    float* smV = smx + T * D;        // 256
    float* smtd = smV + D;           // 64
    float* smDV = smtd + 64;         // 64 (50,51 hold dU,dQ)
    float* smw = smDV + 64;          // 64
    int* smm = (int*)(smw + 64);     // 64

    int b = blockIdx.x, tid = threadIdx.x;
    int warp = tid >> 5, lane = tid & 31;
    const int XBYTES = T * D * 4;    // 51200

    unsigned mbar_a = smem_u32(mbar);
    unsigned smx_a = smem_u32(smx);

    // thread 0: init mbarrier, fence to async proxy, kick bulk copy
    if (tid == 0) {
        asm volatile("mbarrier.init.shared.b64 [%0], 1;" :: "r"(mbar_a) : "memory");
        asm volatile("fence.proxy.async.shared::cta;" ::: "memory");
        asm volatile("mbarrier.arrive.expect_tx.shared.b64 _, [%0], %1;"
                     :: "r"(mbar_a), "r"(XBYTES) : "memory");
        asm volatile("cp.async.bulk.shared::cta.global.mbarrier::complete_tx::bytes "
                     "[%0], [%1], %2, [%3];"
                     :: "r"(smx_a), "l"(x + (size_t)b * T * D), "r"(XBYTES), "r"(mbar_a)
                     : "memory");
    }

    // other loads overlap the bulk copy
    int mq = __ldg(mask + b * T + (T - 1));
    if (mq) {
        int idx = b * D + tid;
        smV[tid] = g_Yp[idx] + g_Yp[BATCH * D + idx] + g_Yp[2 * BATCH * D + idx] +
                   g_Yp[3 * BATCH * D + idx] + g_wv[tid];
    } else {
        smV[tid] = g_ksum[tid];
    }
    if (tid < T) {
        smtd[tid] = td[b * T + tid];
        smm[tid] = mask[b * T + tid];
    }
    __syncthreads();   // mbar init visible to all before wait; smV/td/mask published

    // wait for x tile (acquire)
    {
        unsigned done;
        asm volatile(
            "{\n\t.reg .pred p;\n\t"
            "mbarrier.try_wait.parity.acquire.cta.shared::cta.b64 p, [%1], 0;\n\t"
            "selp.b32 %0, 1, 0, p;\n\t}"
            : "=r"(done) : "r"(mbar_a) : "memory");
        if (!done) {
            asm volatile(
                "{\n\t.reg .pred P1;\n\t"
                "WL_%=:\n\t"
                "mbarrier.try_wait.parity.acquire.cta.shared::cta.b64 P1, [%0], 0, 0x989680;\n\t"
                "@P1 bra.uni WD_%=;\n\t"
                "bra.uni WL_%=;\n\t"
                "WD_%=:\n\t}"
                :: "r"(mbar_a) : "memory");
        }
    }

    float4* smx4 = (float4*)smx;
    float4 va = ((const float4*)smV)[lane];
    float4 vb = ((const float4*)smV)[lane + 32];
    for (int s = warp; s < T; s += 8) {
        float4 x1 = smx4[s * 64 + lane];
        float4 x2 = smx4[s * 64 + 32 + lane];
        float dv = dot4(x1, va) + dot4(x2, vb);
        #pragma unroll
        for (int o = 16; o > 0; o >>= 1) dv += __shfl_xor_sync(0xffffffffu, dv, o);
        if (lane == 0) smDV[s] = dv;
    }
    if (warp == 2 || warp == 3) {
        const float4* w4 = (warp == 2) ? (const float4*)g_u : (const float4*)g_qrs;
        float4 x1 = smx4[(T - 1) * 64 + lane];
        float4 x2 = smx4[(T - 1) * 64 + 32 + lane];
        float dv = dot4(x1, __ldg(w4 + lane)) + dot4(x2, __ldg(w4 + lane + 32));
        #pragma unroll
        for (int o = 16; o > 0; o >>= 1) dv += __shfl_xor_sync(0xffffffffu, dv, o);
        if (lane == 0) smDV[T + (warp - 2)] = dv;
    }
    __syncthreads();

    if (warp == 0) {
        float tdl = smtd[T - 1];
        float s1b = tdl * smDV[T] + g_scal[0];
        float s2b = tdl * smDV[T + 1] + g_scal[1];
        float bksum = g_scal[2];
        float v1 = -3.0e38f, v2 = -3.0e38f;
        if (lane < T) {
            int ms = smm[lane];
            float tds = smtd[lane];
            if (mq) v1 = ms ? (tds * smDV[lane] + s1b) : (NEGC * s2b);
            else    v1 = ms ? (NEGC * (tds * smDV[lane] + bksum)) : (NEGC * NEGC * (float)D);
            v1 *= INV_SQRT_D;
        }
        if (lane + 32 < T) {
            int s = lane + 32;
            int ms = smm[s];
            float tds = smtd[s];
            if (mq) v2 = ms ? (tds * smDV[s] + s1b) : (NEGC * s2b);
            else    v2 = ms ? (NEGC * (tds * smDV[s] + bksum)) : (NEGC * NEGC * (float)D);
            v2 *= INV_SQRT_D;
        }
        float m = fmaxf(v1, v2);
        #pragma unroll
        for (int o = 16; o > 0; o >>= 1) m = fmaxf(m, __shfl_xor_sync(0xffffffffu, m, o));
        float e1 = (lane < T) ? expf(v1 - m) : 0.f;
        float e2 = (lane + 32 < T) ? expf(v2 - m) : 0.f;
        float es = e1 + e2;
        #pragma unroll
        for (int o = 16; o > 0; o >>= 1) es += __shfl_xor_sync(0xffffffffu, es, o);
        float inv = 1.0f / es;
        if (lane < T) smw[lane] = e1 * inv * smtd[lane];
        if (lane + 32 < T) smw[lane + 32] = e2 * inv * smtd[lane + 32];
    }
    __syncthreads();

    int g = tid >> 6, q = tid & 63;
    float4 acc = make_float4(0.f, 0.f, 0.f, 0.f);
    for (int s = g; s < T; s += 4) {
        float w = smw[s];
        float4 xv = smx4[s * 64 + q];
        acc.x += w * xv.x; acc.y += w * xv.y; acc.z += w * xv.z; acc.w += w * xv.w;
    }
    __syncthreads();
    smx4[g * 64 + q] = acc;
    __syncthreads();
    if (tid < 64) {
        float4 p0 = smx4[tid], p1 = smx4[64 + tid];
        float4 p2 = smx4[128 + tid], p3 = smx4[192 + tid];
        float4 r = make_float4(p0.x + p1.x + p2.x + p3.x, p0.y + p1.y + p2.y + p3.y,
                               p0.z + p1.z + p2.z + p3.z, p0.w + p1.w + p2.w + p3.w);
        ((float4*)(g_Z + (size_t)b * D))[tid] = r;
    }
}

// ---------------- K5: reduce out partials + bias ----------------
__global__ __launch_bounds__(256) void reduce_out(const float* __restrict__ bv,
                                                  float* __restrict__ out) {
    int i = blockIdx.x * 256 + threadIdx.x;
    const float4* p = (const float4*)g_Op;
    const int Q = BATCH * D / 4;
    float4 a = p[i], b = p[i + Q], c = p[i + 2 * Q], d = p[i + 3 * Q];
    float4 bb = ((const float4*)bv)[i & 63];
    float4 r = make_float4(a.x + b.x + c.x + d.x + bb.x, a.y + b.y + c.y + d.y + bb.y,
                           a.z + b.z + c.z + d.z + bb.z, a.w + b.w + c.w + d.w + bb.w);
    ((float4*)out)[i] = r;
}

// ---------------- launch ----------------
extern "C" void kernel_launch(void* const* d_in, const int* in_sizes, int n_in,
                              void* d_out, int out_size) {
    const float* x = (const float*)d_in[0];
    const int* mask = (const int*)d_in[1];
    const float* td = (const float*)d_in[2];
    const float* Wq = (const float*)d_in[3];
    const float* bq = (const float*)d_in[4];
    const float* Wk = (const float*)d_in[5];
    const float* bk = (const float*)d_in[6];
    const float* Wv = (const float*)d_in[7];
    const float* bv = (const float*)d_in[8];
    float* out = (float*)d_out;

    // 128B mbar pad + x tile + small arrays
    const int attn_smem = (32 + T * D + D + 64 + 64 + 64 + 64) * 4;  // ~53.4 KB
    cudaFuncSetAttribute(attn_kernel, cudaFuncAttributeMaxDynamicSharedMemorySize, attn_smem);

    dim3 gsk(4, 16, 4);
    prep_kernel<<<dim3(16, 16), 256>>>(Wq, bq, Wk, bk);
    gemm_sk<0, 0, 0><<<gsk, 256>>>(x, td, nullptr);        // Y partials
    attn_kernel<<<BATCH, 256, attn_smem>>>(x, mask, td);
    gemm_sk<1, 1, 1><<<gsk, 256>>>(nullptr, nullptr, Wv);  // out partials
    reduce_out<<<BATCH * D / 4 / 256, 256>>>(bv, out);
}